// round 3
// baseline (speedup 1.0000x reference)
#include <cuda_runtime.h>
#include <math.h>

#define BB 2
#define LL 256
#define DD 128
#define HH 256

// ---------------- scratch (static device globals; no allocation) ----------------
__device__ float g_q  [BB*LL*DD];
__device__ float g_k  [BB*LL*DD];
__device__ float g_v  [BB*LL*DD];
__device__ float g_Z1 [BB*LL*HH];
__device__ float g_X2 [BB*LL*HH];
__device__ float g_g1 [BB*LL*HH];   // lr * gZ1
__device__ float g_g2 [BB*LL*DD];   // lr * gZ2
__device__ float g_lr [BB*LL];
__device__ float g_logm[BB*LL];
__device__ float g_logw[BB*LL];
__device__ float g_ca [BB*LL];      // cumsum log_mom
__device__ float g_wdf[BB*LL];      // exp(cumsum log_wd)
__device__ float g_C  [BB*LL*LL];   // combined wd/mom coefficient matrix
__device__ float g_A  [BB*LL*LL];   // reused for A1 then A2
__device__ float g_Xq2[BB*LL*HH];

__device__ __forceinline__ float softplus_f(float z) {
    return fmaxf(z, 0.f) + log1pf(__expf(-fabsf(z)));
}

// ---------------- stage 0: q,k,v + gate scalar pre-activations ----------------
__global__ void k_qkv(const float* __restrict__ x,
                      const float* __restrict__ Wq, const float* __restrict__ bq,
                      const float* __restrict__ Wk, const float* __restrict__ bk,
                      const float* __restrict__ Wv, const float* __restrict__ bv,
                      const float* __restrict__ Wlr, const float* __restrict__ blr,
                      const float* __restrict__ Wm,  const float* __restrict__ bm,
                      const float* __restrict__ Wwd, const float* __restrict__ bwd)
{
    int t = blockIdx.x;          // b*LL + l
    int d = threadIdx.x;         // 0..127
    __shared__ float xs[DD];
    __shared__ float red[3][DD];
    xs[d] = x[t*DD + d];
    __syncthreads();

    float aq = 0.f, ak = 0.f, av = 0.f;
    const float* wq = Wq + d*DD;
    const float* wk = Wk + d*DD;
    const float* wv = Wv + d*DD;
    #pragma unroll 4
    for (int j = 0; j < DD; j++) {
        float xv = xs[j];
        aq = fmaf(wq[j], xv, aq);
        ak = fmaf(wk[j], xv, ak);
        av = fmaf(wv[j], xv, av);
    }
    g_q[t*DD + d] = aq + bq[d];
    g_k[t*DD + d] = ak + bk[d];
    g_v[t*DD + d] = av + bv[d];

    red[0][d] = xs[d] * Wlr[d];
    red[1][d] = xs[d] * Wm[d];
    red[2][d] = xs[d] * Wwd[d];
    __syncthreads();
    for (int s = 64; s > 0; s >>= 1) {
        if (d < s) {
            red[0][d] += red[0][d+s];
            red[1][d] += red[1][d+s];
            red[2][d] += red[2][d+s];
        }
        __syncthreads();
    }
    if (d == 0) {
        g_lr  [t] =  softplus_f( red[0][0] + blr[0]);
        g_logm[t] = -softplus_f(-(red[1][0] + bm[0]));   // log sigmoid
        g_logw[t] = -softplus_f(-(red[2][0] + bwd[0]));
    }
}

// ---------------- stage 1: inclusive scans of log_mom / log_wd ----------------
__global__ void k_scan()
{
    int b = blockIdx.x;
    int i = threadIdx.x;   // 0..255
    __shared__ float sa[LL], sw[LL];
    sa[i] = g_logm[b*LL + i];
    sw[i] = g_logw[b*LL + i];
    __syncthreads();
    for (int off = 1; off < LL; off <<= 1) {
        float va = (i >= off) ? sa[i-off] : 0.f;
        float vw = (i >= off) ? sw[i-off] : 0.f;
        __syncthreads();
        sa[i] += va;
        sw[i] += vw;
        __syncthreads();
    }
    g_ca [b*LL + i] = sa[i];
    g_wdf[b*LL + i] = __expf(sw[i]);
}

// ---------------- stage 2: Z1 = k W1^T + b1 ; X2 = silu(Z1) ----------------
__global__ void k_z1(const float* __restrict__ W1, const float* __restrict__ b1)
{
    int t = blockIdx.x;
    int h = threadIdx.x;   // 0..255
    __shared__ float ks[DD];
    if (h < DD) ks[h] = g_k[t*DD + h];
    __syncthreads();
    float a = 0.f;
    const float* w = W1 + h*DD;
    #pragma unroll 4
    for (int j = 0; j < DD; j++) a = fmaf(w[j], ks[j], a);
    float z = a + b1[h];
    g_Z1[t*HH + h] = z;
    float sig = 1.f / (1.f + __expf(-z));
    g_X2[t*HH + h] = z * sig;
}

// ---------------- stage 3: Z2, gZ2 -> g2 ; gX2, gZ1 -> g1 ----------------
__global__ void k_grad(const float* __restrict__ W2, const float* __restrict__ b2)
{
    int t = blockIdx.x;
    int h = threadIdx.x;   // 0..255
    __shared__ float xs2[HH];
    __shared__ float gz2s[DD];
    xs2[h] = g_X2[t*HH + h];
    __syncthreads();
    float lr = g_lr[t];
    if (h < DD) {
        float a = 0.f;
        const float* w = W2 + h*HH;
        #pragma unroll 4
        for (int j = 0; j < HH; j++) a = fmaf(w[j], xs2[j], a);
        float gz2 = a + b2[h] - g_v[t*DD + h];
        gz2s[h] = gz2;
        g_g2[t*DD + h] = lr * gz2;
    }
    __syncthreads();
    float a = 0.f;
    #pragma unroll 4
    for (int dd = 0; dd < DD; dd++) a = fmaf(gz2s[dd], W2[dd*HH + h], a);
    float z1  = g_Z1[t*HH + h];
    float sig = 1.f / (1.f + __expf(-z1));
    float s   = z1 * sig;
    float sb  = s + sig * (1.f - s);   // module's silu_backward (== exact derivative)
    g_g1[t*HH + h] = lr * a * sb;
}

// ---------------- stage 4: combined coefficient matrix C ----------------
// C[l,m] = d_l * C[l-1,m] + exp(ca[l]-ca[m]),  C[m,m]=1,  C=0 above diagonal.
__global__ void k_C()
{
    int b = blockIdx.x;
    int m = threadIdx.x;   // column
    __shared__ float cas[LL], ds[LL];
    cas[m] = g_ca[b*LL + m];
    ds[m]  = __expf(g_logw[b*LL + m]);
    __syncthreads();
    float* Cb = g_C + b*LL*LL;
    for (int l = 0; l < m; l++) Cb[l*LL + m] = 0.f;
    float c = 0.f;
    float cam = cas[m];
    for (int l = m; l < LL; l++) {
        c = fmaf(ds[l], c, __expf(cas[l] - cam));
        Cb[l*LL + m] = c;
    }
}

// ---------------- stage 5: A1[l,m] = C[l,m]*(k[m].q[l] + 1) ----------------
__global__ void k_A1()
{
    int t = blockIdx.x;
    int b = t / LL;
    int l = t % LL;
    int m = threadIdx.x;
    __shared__ float qs[DD];
    if (m < DD) qs[m] = g_q[t*DD + m];
    __syncthreads();
    float r = 0.f;
    if (m <= l) {
        const float* kk = g_k + (b*LL + m)*DD;
        float dot = 0.f;
        #pragma unroll 4
        for (int j = 0; j < DD; j++) dot = fmaf(kk[j], qs[j], dot);
        r = g_C[t*LL + m] * (dot + 1.f);
    }
    g_A[t*LL + m] = r;
}

// ---------------- stage 6: Zq1 = A1 @ g1 + wdf*(W1 q + b1) ; Xq2 = silu ----------------
__global__ void k_zq1(const float* __restrict__ W1, const float* __restrict__ b1)
{
    int t = blockIdx.x;
    int b = t / LL;
    int l = t % LL;
    int h = threadIdx.x;   // 0..255
    __shared__ float As[LL];
    __shared__ float qs[DD];
    As[h] = g_A[t*LL + h];
    if (h < DD) qs[h] = g_q[t*DD + h];
    __syncthreads();
    float acc = 0.f;
    const float* g1b = g_g1 + b*LL*HH + h;
    for (int m = 0; m <= l; m++) acc = fmaf(As[m], g1b[m*HH], acc);
    float aw = 0.f;
    const float* w = W1 + h*DD;
    #pragma unroll 4
    for (int j = 0; j < DD; j++) aw = fmaf(w[j], qs[j], aw);
    float z = acc + g_wdf[t] * (aw + b1[h]);
    float sig = 1.f / (1.f + __expf(-z));
    g_Xq2[t*HH + h] = z * sig;
}

// ---------------- stage 7: A2[l,m] = C[l,m]*(X2[m].Xq2[l] + 1) ----------------
__global__ void k_A2()
{
    int t = blockIdx.x;
    int b = t / LL;
    int l = t % LL;
    int m = threadIdx.x;
    __shared__ float xq[HH];
    xq[m] = g_Xq2[t*HH + m];
    __syncthreads();
    float r = 0.f;
    if (m <= l) {
        const float* x2 = g_X2 + (b*LL + m)*HH;
        float dot = 0.f;
        #pragma unroll 4
        for (int j = 0; j < HH; j++) dot = fmaf(x2[j], xq[j], dot);
        r = g_C[t*LL + m] * (dot + 1.f);
    }
    g_A[t*LL + m] = r;
}

// ---------------- stage 8: Zq2 = A2 @ g2 + wdf*(W2 Xq2 + b2) -> out ----------------
__global__ void k_zq2(const float* __restrict__ W2, const float* __restrict__ b2,
                      float* __restrict__ out)
{
    int t = blockIdx.x;
    int b = t / LL;
    int l = t % LL;
    int d = threadIdx.x;   // 0..127
    __shared__ float As[LL];
    __shared__ float xq[HH];
    As[d]      = g_A[t*LL + d];
    As[d + DD] = g_A[t*LL + d + DD];
    xq[d]      = g_Xq2[t*HH + d];
    xq[d + DD] = g_Xq2[t*HH + d + DD];
    __syncthreads();
    float acc = 0.f;
    const float* g2b = g_g2 + b*LL*DD + d;
    for (int m = 0; m <= l; m++) acc = fmaf(As[m], g2b[m*DD], acc);
    float aw = 0.f;
    const float* w = W2 + d*HH;
    #pragma unroll 4
    for (int j = 0; j < HH; j++) aw = fmaf(w[j], xq[j], aw);
    out[t*DD + d] = acc + g_wdf[t] * (aw + b2[d]);
}

// ---------------- launch ----------------
extern "C" void kernel_launch(void* const* d_in, const int* in_sizes, int n_in,
                              void* d_out, int out_size)
{
    (void)in_sizes; (void)n_in; (void)out_size;
    const float* x   = (const float*)d_in[0];
    const float* W1  = (const float*)d_in[1];
    const float* b1  = (const float*)d_in[2];
    const float* W2  = (const float*)d_in[3];
    const float* b2  = (const float*)d_in[4];
    const float* Wq  = (const float*)d_in[5];
    const float* bq  = (const float*)d_in[6];
    const float* Wk  = (const float*)d_in[7];
    const float* bk  = (const float*)d_in[8];
    const float* Wv  = (const float*)d_in[9];
    const float* bv  = (const float*)d_in[10];
    const float* Wlr = (const float*)d_in[11];
    const float* blr = (const float*)d_in[12];
    const float* Wm  = (const float*)d_in[13];
    const float* bm  = (const float*)d_in[14];
    const float* Wwd = (const float*)d_in[15];
    const float* bwd = (const float*)d_in[16];
    float* out = (float*)d_out;

    k_qkv <<<BB*LL, DD>>>(x, Wq, bq, Wk, bk, Wv, bv, Wlr, blr, Wm, bm, Wwd, bwd);
    k_scan<<<BB, LL>>>();
    k_z1  <<<BB*LL, HH>>>(W1, b1);
    k_grad<<<BB*LL, HH>>>(W2, b2);
    k_C   <<<BB, LL>>>();
    k_A1  <<<BB*LL, LL>>>();
    k_zq1 <<<BB*LL, HH>>>(W1, b1);
    k_A2  <<<BB*LL, LL>>>();
    k_zq2 <<<BB*LL, DD>>>(W2, b2, out);
}

// round 5
// speedup vs baseline: 4.1945x; 4.1945x over previous
#include <cuda_runtime.h>
#include <math.h>

#define BB 2
#define LL 256
#define DD 128
#define HH 256
#define NTOK (BB*LL)
#define BK 16

// ---------------- scratch (static device globals; no allocation) ----------------
__device__ __align__(16) float g_q  [NTOK*DD];
__device__ __align__(16) float g_k  [NTOK*DD];
__device__ __align__(16) float g_v  [NTOK*DD];
__device__ __align__(16) float g_Z1 [NTOK*HH];
__device__ __align__(16) float g_X2 [NTOK*HH];
__device__ __align__(16) float g_g1 [NTOK*HH];   // lr * gZ1
__device__ __align__(16) float g_g2 [NTOK*DD];   // lr * gZ2
__device__ __align__(16) float g_Xq2[NTOK*HH];
__device__ __align__(16) float g_C  [BB*LL*LL];  // combined wd/mom coefficient matrix
__device__ __align__(16) float g_A  [BB*LL*LL];  // A1 then A2
__device__ float g_lr [NTOK];
__device__ float g_am [NTOK];   // momentum sigmoid a_l
__device__ float g_dw [NTOK];   // weight-decay sigmoid d_l
__device__ float g_wdf[NTOK];   // prefix product of d

__device__ __forceinline__ float softplus_f(float z) {
    return fmaxf(z, 0.f) + log1pf(__expf(-fabsf(z)));
}
__device__ __forceinline__ float sigmoid_f(float z) {
    return 1.f / (1.f + __expf(-z));
}

// ================= tiled-GEMM building blocks (BM=BN=64, BK=16, 256 thr) =======

// load a 64x16 tile of P (row-major, rows of length ld) transposed into S[k][r]
__device__ __forceinline__ void ld_trans(const float* __restrict__ P, int ld,
                                         int r0, int k0, float S[BK][68], int tid)
{
    int r  = tid >> 2;          // 0..63
    int k4 = (tid & 3) << 2;    // 0,4,8,12
    float4 v = *(const float4*)(P + (r0 + r) * ld + k0 + k4);
    S[k4 + 0][r] = v.x;
    S[k4 + 1][r] = v.y;
    S[k4 + 2][r] = v.z;
    S[k4 + 3][r] = v.w;
}

// load a 16x64 tile of P (row-major K x N, rows of length ld) directly into S[k][n]
__device__ __forceinline__ void ld_norm(const float* __restrict__ P, int ld,
                                        int k0, int n0, float S[BK][68], int tid)
{
    int k  = tid >> 4;          // 0..15
    int n4 = (tid & 15) << 2;   // 0..60
    *(float4*)&S[k][n4] = *(const float4*)(P + (k0 + k) * ld + n0 + n4);
}

__device__ __forceinline__ void mma16(const float SA[BK][68], const float SB[BK][68],
                                      float acc[4][4], int ty, int tx)
{
    #pragma unroll
    for (int k = 0; k < BK; k++) {
        float4 a = *(const float4*)&SA[k][ty << 2];
        float4 b = *(const float4*)&SB[k][tx << 2];
        float av[4] = {a.x, a.y, a.z, a.w};
        float bv[4] = {b.x, b.y, b.z, b.w};
        #pragma unroll
        for (int i = 0; i < 4; i++)
            #pragma unroll
            for (int j = 0; j < 4; j++)
                acc[i][j] = fmaf(av[i], bv[j], acc[i][j]);
    }
}

// A (row-major MxK) @ B^T (B given as N rows of length K)
#define GEMM_TT(Aptr, lda, Bptr, ldb, K, m0, n0, acc)                    \
    for (int k0 = 0; k0 < (K); k0 += BK) {                               \
        ld_trans((Aptr), (lda), (m0), k0, As, tid);                      \
        ld_trans((Bptr), (ldb), (n0), k0, Bs, tid);                      \
        __syncthreads();                                                 \
        mma16(As, Bs, acc, ty, tx);                                      \
        __syncthreads();                                                 \
    }

// A (row-major MxK) @ B (row-major KxN)
#define GEMM_TN(Aptr, lda, Bptr, ldb, K, m0, n0, acc)                    \
    for (int k0 = 0; k0 < (K); k0 += BK) {                               \
        ld_trans((Aptr), (lda), (m0), k0, As, tid);                      \
        ld_norm ((Bptr), (ldb), k0, (n0), Bs, tid);                      \
        __syncthreads();                                                 \
        mma16(As, Bs, acc, ty, tx);                                      \
        __syncthreads();                                                 \
    }

#define TILE_PROLOG                                                      \
    __shared__ float As[BK][68], Bs[BK][68];                             \
    int tid = threadIdx.x;                                               \
    int ty = tid >> 4, tx = tid & 15;                                    \
    float acc[4][4] = {};

// ================= stage kernels ==============================================

// ---- gates: lr, momentum sigmoid, wd sigmoid (one warp per token) ----
__global__ __launch_bounds__(256) void k_gates(
    const float* __restrict__ x,
    const float* __restrict__ Wlr, const float* __restrict__ blr,
    const float* __restrict__ Wm,  const float* __restrict__ bm,
    const float* __restrict__ Wwd, const float* __restrict__ bwd)
{
    int w = threadIdx.x >> 5, lane = threadIdx.x & 31;
    int t = blockIdx.x * 8 + w;
    float s0 = 0.f, s1 = 0.f, s2 = 0.f;
    #pragma unroll
    for (int i = 0; i < 4; i++) {
        int j = lane + 32 * i;
        float xv = x[t * DD + j];
        s0 = fmaf(xv, Wlr[j], s0);
        s1 = fmaf(xv, Wm [j], s1);
        s2 = fmaf(xv, Wwd[j], s2);
    }
    #pragma unroll
    for (int o = 16; o; o >>= 1) {
        s0 += __shfl_xor_sync(0xffffffffu, s0, o);
        s1 += __shfl_xor_sync(0xffffffffu, s1, o);
        s2 += __shfl_xor_sync(0xffffffffu, s2, o);
    }
    if (lane == 0) {
        g_lr[t] = softplus_f(s0 + blr[0]);
        g_am[t] = sigmoid_f(s1 + bm[0]);
        g_dw[t] = sigmoid_f(s2 + bwd[0]);
    }
}

// ---- scan (prefix product of d) + combined coefficient matrix C ----
// C[l,m] = d_l*C[l-1,m] + e,  e = prod_{m<i<=l} a_i  (MUFU-free recurrence)
__global__ __launch_bounds__(256) void k_scanC()
{
    int b = blockIdx.x;
    int m = threadIdx.x;
    __shared__ float ds[LL], as_[LL], p[LL];
    float d = g_dw[b * LL + m];
    ds[m]  = d;
    as_[m] = g_am[b * LL + m];
    p[m]   = d;
    __syncthreads();
    for (int off = 1; off < LL; off <<= 1) {
        float v = (m >= off) ? p[m - off] : 1.f;
        __syncthreads();
        p[m] *= v;
        __syncthreads();
    }
    g_wdf[b * LL + m] = p[m];

    float* Cb = g_C + b * LL * LL;
    float c = 0.f, e = 0.f;
    for (int l = 0; l < LL; l++) {
        e *= as_[l];
        if (l == m) e = 1.f;
        c = fmaf(ds[l], c, e);
        Cb[l * LL + m] = c;   // uniform l -> coalesced
    }
}

// ---- q,k,v projections: X[512,128] @ W^T, N=384 folded ----
__global__ __launch_bounds__(256) void gemm_qkv(
    const float* __restrict__ x,
    const float* __restrict__ Wq, const float* __restrict__ bq,
    const float* __restrict__ Wk, const float* __restrict__ bk,
    const float* __restrict__ Wv, const float* __restrict__ bv)
{
    TILE_PROLOG
    int m0 = blockIdx.x * 64;
    int n0g = blockIdx.y * 64;
    int sel = n0g >> 7;
    int n0  = n0g & 127;
    const float* W    = (sel == 0) ? Wq : (sel == 1) ? Wk : Wv;
    const float* bias = (sel == 0) ? bq : (sel == 1) ? bk : bv;
    float* out        = (sel == 0) ? g_q : (sel == 1) ? g_k : g_v;
    GEMM_TT(x, DD, W, DD, DD, m0, n0, acc)
    #pragma unroll
    for (int i = 0; i < 4; i++) {
        int t = m0 + (ty << 2) + i;
        #pragma unroll
        for (int j = 0; j < 4; j++) {
            int n = n0 + (tx << 2) + j;
            out[t * DD + n] = acc[i][j] + bias[n];
        }
    }
}

// ---- Z1 = k @ W1^T + b1 ; X2 = silu(Z1) ----
__global__ __launch_bounds__(256) void gemm_z1(
    const float* __restrict__ W1, const float* __restrict__ b1)
{
    TILE_PROLOG
    int m0 = blockIdx.x * 64, n0 = blockIdx.y * 64;
    GEMM_TT(g_k, DD, W1, DD, DD, m0, n0, acc)
    #pragma unroll
    for (int i = 0; i < 4; i++) {
        int t = m0 + (ty << 2) + i;
        #pragma unroll
        for (int j = 0; j < 4; j++) {
            int n = n0 + (tx << 2) + j;
            float z = acc[i][j] + b1[n];
            g_Z1[t * HH + n] = z;
            g_X2[t * HH + n] = z * sigmoid_f(z);
        }
    }
}

// ---- gZ2 = X2 @ W2^T + b2 - v ;  g2 = lr * gZ2 ----
__global__ __launch_bounds__(256) void gemm_z2(
    const float* __restrict__ W2, const float* __restrict__ b2)
{
    TILE_PROLOG
    int m0 = blockIdx.x * 64, n0 = blockIdx.y * 64;
    GEMM_TT(g_X2, HH, W2, HH, HH, m0, n0, acc)
    #pragma unroll
    for (int i = 0; i < 4; i++) {
        int t = m0 + (ty << 2) + i;
        float lr = g_lr[t];
        #pragma unroll
        for (int j = 0; j < 4; j++) {
            int n = n0 + (tx << 2) + j;
            float gz = acc[i][j] + b2[n] - g_v[t * DD + n];
            g_g2[t * DD + n] = lr * gz;
        }
    }
}

// ---- lr*gX2 = g2 @ W2 ; g1 = (lr*gX2) * silu_bwd(Z1) ----
__global__ __launch_bounds__(256) void gemm_gx2(
    const float* __restrict__ W2)
{
    TILE_PROLOG
    int m0 = blockIdx.x * 64, n0 = blockIdx.y * 64;
    GEMM_TN(g_g2, DD, W2, HH, DD, m0, n0, acc)
    #pragma unroll
    for (int i = 0; i < 4; i++) {
        int t = m0 + (ty << 2) + i;
        #pragma unroll
        for (int j = 0; j < 4; j++) {
            int n = n0 + (tx << 2) + j;
            float z1  = g_Z1[t * HH + n];
            float sig = sigmoid_f(z1);
            float s   = z1 * sig;
            float sb  = s + sig * (1.f - s);   // module's silu_backward
            g_g1[t * HH + n] = acc[i][j] * sb;
        }
    }
}

// ---- A1[l,m] = C[l,m]*(q_l . k_m + 1), masked (per batch) ----
__global__ __launch_bounds__(256) void gemm_A1()
{
    __shared__ float As[BK][68], Bs[BK][68];
    int tid = threadIdx.x;
    int ty = tid >> 4, tx = tid & 15;
    int b  = blockIdx.z;
    int l0 = blockIdx.x * 64, n0 = blockIdx.y * 64;
    if (n0 > l0 + 63) {   // tile entirely above diagonal -> zeros
        #pragma unroll
        for (int i = 0; i < 4; i++) {
            int t = b * LL + l0 + (ty << 2) + i;
            #pragma unroll
            for (int j = 0; j < 4; j++)
                g_A[t * LL + n0 + (tx << 2) + j] = 0.f;
        }
        return;
    }
    float acc[4][4] = {};
    GEMM_TT(g_q + b * LL * DD, DD, g_k + b * LL * DD, DD, DD, l0, n0, acc)
    #pragma unroll
    for (int i = 0; i < 4; i++) {
        int l = l0 + (ty << 2) + i;
        int t = b * LL + l;
        #pragma unroll
        for (int j = 0; j < 4; j++) {
            int m = n0 + (tx << 2) + j;
            float cc = g_C[t * LL + m];
            g_A[t * LL + m] = (m <= l) ? cc * (acc[i][j] + 1.f) : 0.f;
        }
    }
}

// ---- Zq1 = A1 @ g1 + wdf*(q @ W1^T + b1) ; Xq2 = silu ----
__global__ __launch_bounds__(256) void gemm_zq1(
    const float* __restrict__ W1, const float* __restrict__ b1)
{
    __shared__ float As[BK][68], Bs[BK][68];
    int tid = threadIdx.x;
    int ty = tid >> 4, tx = tid & 15;
    int b  = blockIdx.z;
    int l0 = blockIdx.x * 64, n0 = blockIdx.y * 64;
    float acc1[4][4] = {}, acc2[4][4] = {};
    GEMM_TN(g_A + b * LL * LL, LL, g_g1 + b * LL * HH, HH, LL, l0, n0, acc1)
    GEMM_TT(g_q + b * LL * DD, DD, W1, DD, DD, l0, n0, acc2)
    #pragma unroll
    for (int i = 0; i < 4; i++) {
        int t = b * LL + l0 + (ty << 2) + i;
        float wdf = g_wdf[t];
        #pragma unroll
        for (int j = 0; j < 4; j++) {
            int n = n0 + (tx << 2) + j;
            float z = acc1[i][j] + wdf * (acc2[i][j] + b1[n]);
            g_Xq2[t * HH + n] = z * sigmoid_f(z);
        }
    }
}

// ---- A2[l,m] = C[l,m]*(Xq2_l . X2_m + 1), masked (per batch) ----
__global__ __launch_bounds__(256) void gemm_A2()
{
    __shared__ float As[BK][68], Bs[BK][68];
    int tid = threadIdx.x;
    int ty = tid >> 4, tx = tid & 15;
    int b  = blockIdx.z;
    int l0 = blockIdx.x * 64, n0 = blockIdx.y * 64;
    if (n0 > l0 + 63) {
        #pragma unroll
        for (int i = 0; i < 4; i++) {
            int t = b * LL + l0 + (ty << 2) + i;
            #pragma unroll
            for (int j = 0; j < 4; j++)
                g_A[t * LL + n0 + (tx << 2) + j] = 0.f;
        }
        return;
    }
    float acc[4][4] = {};
    GEMM_TT(g_Xq2 + b * LL * HH, HH, g_X2 + b * LL * HH, HH, HH, l0, n0, acc)
    #pragma unroll
    for (int i = 0; i < 4; i++) {
        int l = l0 + (ty << 2) + i;
        int t = b * LL + l;
        #pragma unroll
        for (int j = 0; j < 4; j++) {
            int m = n0 + (tx << 2) + j;
            float cc = g_C[t * LL + m];
            g_A[t * LL + m] = (m <= l) ? cc * (acc[i][j] + 1.f) : 0.f;
        }
    }
}

// ---- out = A2 @ g2 + wdf*(Xq2 @ W2^T + b2) ----
__global__ __launch_bounds__(256) void gemm_zq2(
    const float* __restrict__ W2, const float* __restrict__ b2,
    float* __restrict__ out)
{
    __shared__ float As[BK][68], Bs[BK][68];
    int tid = threadIdx.x;
    int ty = tid >> 4, tx = tid & 15;
    int b  = blockIdx.z;
    int l0 = blockIdx.x * 64, n0 = blockIdx.y * 64;
    float acc1[4][4] = {}, acc2[4][4] = {};
    GEMM_TN(g_A + b * LL * LL, LL, g_g2 + b * LL * DD, DD, LL, l0, n0, acc1)
    GEMM_TT(g_Xq2 + b * LL * HH, HH, W2, HH, HH, l0, n0, acc2)
    #pragma unroll
    for (int i = 0; i < 4; i++) {
        int t = b * LL + l0 + (ty << 2) + i;
        float wdf = g_wdf[t];
        #pragma unroll
        for (int j = 0; j < 4; j++) {
            int n = n0 + (tx << 2) + j;
            out[t * DD + n] = acc1[i][j] + wdf * (acc2[i][j] + b2[n]);
        }
    }
}

// ================= launch ======================================================
extern "C" void kernel_launch(void* const* d_in, const int* in_sizes, int n_in,
                              void* d_out, int out_size)
{
    (void)in_sizes; (void)n_in; (void)out_size;
    const float* x   = (const float*)d_in[0];
    const float* W1  = (const float*)d_in[1];
    const float* b1  = (const float*)d_in[2];
    const float* W2  = (const float*)d_in[3];
    const float* b2  = (const float*)d_in[4];
    const float* Wq  = (const float*)d_in[5];
    const float* bq  = (const float*)d_in[6];
    const float* Wk  = (const float*)d_in[7];
    const float* bk  = (const float*)d_in[8];
    const float* Wv  = (const float*)d_in[9];
    const float* bv  = (const float*)d_in[10];
    const float* Wlr = (const float*)d_in[11];
    const float* blr = (const float*)d_in[12];
    const float* Wm  = (const float*)d_in[13];
    const float* bm  = (const float*)d_in[14];
    const float* Wwd = (const float*)d_in[15];
    const float* bwd = (const float*)d_in[16];
    float* out = (float*)d_out;

    k_gates  <<<NTOK / 8, 256>>>(x, Wlr, blr, Wm, bm, Wwd, bwd);
    k_scanC  <<<BB, 256>>>();
    gemm_qkv <<<dim3(8, 6), 256>>>(x, Wq, bq, Wk, bk, Wv, bv);
    gemm_z1  <<<dim3(8, 4), 256>>>(W1, b1);
    gemm_z2  <<<dim3(8, 2), 256>>>(W2, b2);
    gemm_gx2 <<<dim3(8, 4), 256>>>(W2);
    gemm_A1  <<<dim3(4, 4, BB), 256>>>();
    gemm_zq1 <<<dim3(4, 4, BB), 256>>>(W1, b1);
    gemm_A2  <<<dim3(4, 4, BB), 256>>>();
    gemm_zq2 <<<dim3(4, 2, BB), 256>>>(W2, b2, out);
}

// round 8
// speedup vs baseline: 5.2652x; 1.2553x over previous
#include <cuda_runtime.h>
#include <math.h>

#define BB 2
#define LL 256
#define DD 128
#define HH 256
#define NTOK (BB*LL)
#define GRID 148
#define SMS  544   // 16 rows * 34 stride

// ---------------- scratch (static device globals; no allocation) ----------------
__device__ __align__(16) float g_q  [NTOK*DD];
__device__ __align__(16) float g_k  [NTOK*DD];
__device__ __align__(16) float g_v  [NTOK*DD];
__device__ __align__(16) float g_Z1 [NTOK*HH];
__device__ __align__(16) float g_X2 [NTOK*HH];
__device__ __align__(16) float g_g1 [NTOK*HH];
__device__ __align__(16) float g_g2 [NTOK*DD];
__device__ __align__(16) float g_Xq2[NTOK*HH];
__device__ __align__(16) float g_C  [BB*LL*LL];
__device__ __align__(16) float g_A  [BB*LL*LL];
__device__ float g_lr [NTOK];
__device__ float g_wdf[NTOK];
__device__ unsigned g_cnt = 0;
__device__ unsigned g_gen = 0;

__device__ __forceinline__ float softplus_f(float z) {
    return fmaxf(z, 0.f) + log1pf(__expf(-fabsf(z)));
}
__device__ __forceinline__ float sigmoid_f(float z) {
    return 1.f / (1.f + __expf(-z));
}

// sense-reversing grid barrier (all GRID blocks resident: GRID <= #SMs)
__device__ __forceinline__ void gbar() {
    __syncthreads();
    if (threadIdx.x == 0) {
        __threadfence();
        unsigned gen = *(volatile unsigned*)&g_gen;
        unsigned prev = atomicAdd(&g_cnt, 1u);
        if (prev == GRID - 1) {
            g_cnt = 0;
            __threadfence();
            *(volatile unsigned*)&g_gen = gen + 1;
        } else {
            while (*(volatile unsigned*)&g_gen == gen) __nanosleep(64);
            __threadfence();
        }
    }
    __syncthreads();
}

// ---------------- 32x32 tile GEMM pieces (BK=16, 256 threads, 2x2 micro) -------
// As[k][m] (transposed A strip): coalesced 64B-chunk global reads
__device__ __forceinline__ void ldT(const float* __restrict__ P, int ld,
                                    int r0, int k0, float* S, int tid)
{
    int r  = tid >> 3;          // 0..31
    int k2 = (tid & 7) << 1;    // 0..14
    float2 v = *(const float2*)(P + (r0 + r) * ld + k0 + k2);
    S[ k2      * 34 + r] = v.x;
    S[(k2 + 1) * 34 + r] = v.y;
}
// Bs[k][n] direct from row-major KxN
__device__ __forceinline__ void ldN(const float* __restrict__ P, int ld,
                                    int k0, int n0, float* S, int tid)
{
    int k  = tid >> 4;          // 0..15
    int n2 = (tid & 15) << 1;   // 0..30
    *(float2*)(S + k * 34 + n2) = *(const float2*)(P + (k0 + k) * ld + n0 + n2);
}

__device__ __forceinline__ void mma16(const float* As, const float* Bs,
                                      int ty, int tx, float acc[2][2])
{
    #pragma unroll
    for (int k = 0; k < 16; k++) {
        float2 a = *(const float2*)(As + k * 34 + (ty << 1));
        float2 b = *(const float2*)(Bs + k * 34 + (tx << 1));
        acc[0][0] = fmaf(a.x, b.x, acc[0][0]);
        acc[0][1] = fmaf(a.x, b.y, acc[0][1]);
        acc[1][0] = fmaf(a.y, b.x, acc[1][0]);
        acc[1][1] = fmaf(a.y, b.y, acc[1][1]);
    }
}

// C = A(MxK,row-major) @ B  ; TB=true: B given as N rows of length K (B^T)
template<bool TB>
__device__ __forceinline__ void gemm(const float* __restrict__ A, int lda,
                                     const float* __restrict__ B, int ldb,
                                     int K, int m0, int n0,
                                     float acc[2][2], float* sm, int tid, int ty, int tx)
{
    float* As = sm;
    float* Bs = sm + SMS;
    for (int k0 = 0; k0 < K; k0 += 16) {
        ldT(A, lda, m0, k0, As, tid);
        if (TB) ldT(B, ldb, n0, k0, Bs, tid);
        else    ldN(B, ldb, k0, n0, Bs, tid);
        __syncthreads();
        mma16(As, Bs, ty, tx, acc);
        __syncthreads();
    }
}

// map t in [0,36) to lower-triangular (i,j), j<=i, i in [0,8)
__device__ __forceinline__ void tri_map(int t, int& i, int& j) {
    i = 0;
    while ((i + 1) * (i + 2) / 2 <= t) i++;
    j = t - i * (i + 1) / 2;
}

// ================= fused persistent kernel =====================================
__global__ void __launch_bounds__(256, 1) fused(
    const float* __restrict__ x,
    const float* __restrict__ W1, const float* __restrict__ b1,
    const float* __restrict__ W2, const float* __restrict__ b2,
    const float* __restrict__ Wq, const float* __restrict__ bq,
    const float* __restrict__ Wk, const float* __restrict__ bk,
    const float* __restrict__ Wv, const float* __restrict__ bv,
    const float* __restrict__ Wlr, const float* __restrict__ blr,
    const float* __restrict__ Wm,  const float* __restrict__ bm,
    const float* __restrict__ Wwd, const float* __restrict__ bwd,
    float* __restrict__ out)
{
    __shared__ float sm[2 * SMS];
    const int tid = threadIdx.x;
    const int ty = tid >> 4, tx = tid & 15;

    // ================= P1: qkv GEMM (192 tiles) + gates/scan/C (2 blocks) ======
    for (int t = blockIdx.x; t < 194; t += GRID) {
        if (t < 192) {
            int m0 = (t & 15) * 32;
            int c0 = (t >> 4) * 32;
            int sel = c0 >> 7;
            int n0  = c0 & 127;
            const float* W    = (sel == 0) ? Wq : (sel == 1) ? Wk : Wv;
            const float* bias = (sel == 0) ? bq : (sel == 1) ? bk : bv;
            float* o          = (sel == 0) ? g_q : (sel == 1) ? g_k : g_v;
            float acc[2][2] = {};
            gemm<true>(x, DD, W, DD, DD, m0, n0, acc, sm, tid, ty, tx);
            #pragma unroll
            for (int i = 0; i < 2; i++) {
                int row = m0 + (ty << 1) + i;
                int n   = n0 + (tx << 1);
                float2 r = {acc[i][0] + bias[n], acc[i][1] + bias[n + 1]};
                *(float2*)&o[row * DD + n] = r;
            }
        } else {
            // gates + prefix products + C matrix for batch b
            int b = t - 192;
            int m = tid;
            const float* xr = x + (b * LL + m) * DD;
            float s0 = 0.f, s1 = 0.f, s2 = 0.f;
            #pragma unroll 4
            for (int j = 0; j < DD; j++) {
                float xv = xr[j];
                s0 = fmaf(xv, Wlr[j], s0);
                s1 = fmaf(xv, Wm [j], s1);
                s2 = fmaf(xv, Wwd[j], s2);
            }
            g_lr[b * LL + m] = softplus_f(s0 + blr[0]);
            float a = sigmoid_f(s1 + bm[0]);
            float d = sigmoid_f(s2 + bwd[0]);
            float* ds  = sm;
            float* as_ = sm + 256;
            float* p   = sm + 512;
            ds[m] = d; as_[m] = a; p[m] = d;
            __syncthreads();
            for (int off = 1; off < LL; off <<= 1) {
                float v = (m >= off) ? p[m - off] : 1.f;
                __syncthreads();
                p[m] *= v;
                __syncthreads();
            }
            g_wdf[b * LL + m] = p[m];
            // C[l,m] = d_l*C[l-1,m] + prod_{m<i<=l} a_i ; zero above diagonal
            float* Cb = g_C + b * LL * LL;
            float c = 0.f, e = 0.f;
            for (int l = 0; l < LL; l++) {
                e *= as_[l];
                if (l == m) e = 1.f;
                c = fmaf(ds[l], c, e);
                Cb[l * LL + m] = c;
            }
            __syncthreads();
        }
    }
    gbar();

    // ================= P2: Z1/X2 (128 tiles) + A1 = C.(qk^T+1) (72 tiles) ======
    for (int t = blockIdx.x; t < 200; t += GRID) {
        if (t < 128) {
            int m0 = (t & 15) * 32, n0 = (t >> 4) * 32;
            float acc[2][2] = {};
            gemm<true>(g_k, DD, W1, DD, DD, m0, n0, acc, sm, tid, ty, tx);
            #pragma unroll
            for (int i = 0; i < 2; i++) {
                int row = m0 + (ty << 1) + i;
                int n   = n0 + (tx << 1);
                float z0 = acc[i][0] + b1[n];
                float z1 = acc[i][1] + b1[n + 1];
                *(float2*)&g_Z1[row * HH + n] = {z0, z1};
                *(float2*)&g_X2[row * HH + n] = {z0 * sigmoid_f(z0), z1 * sigmoid_f(z1)};
            }
        } else {
            int tt = t - 128;
            int b = tt / 36;
            int i, j; tri_map(tt % 36, i, j);
            int l0 = i * 32, m0 = j * 32;
            const float* qb = g_q + b * LL * DD;
            const float* kb = g_k + b * LL * DD;
            float acc[2][2] = {};
            gemm<true>(qb, DD, kb, DD, DD, l0, m0, acc, sm, tid, ty, tx);
            #pragma unroll
            for (int ii = 0; ii < 2; ii++) {
                int l = l0 + (ty << 1) + ii;
                int mm = m0 + (tx << 1);
                const float* Crow = g_C + (b * LL + l) * LL + mm;
                float2 cc = *(const float2*)Crow;
                float2 r = {cc.x * (acc[ii][0] + 1.f), cc.y * (acc[ii][1] + 1.f)};
                *(float2*)&g_A[(b * LL + l) * LL + mm] = r;
            }
        }
    }
    gbar();

    // ================= P3: g2 = lr*(X2 W2^T + b2 - v)  (64 tiles) ==============
    for (int t = blockIdx.x; t < 64; t += GRID) {
        int m0 = (t & 15) * 32, n0 = (t >> 4) * 32;
        float acc[2][2] = {};
        gemm<true>(g_X2, HH, W2, HH, HH, m0, n0, acc, sm, tid, ty, tx);
        #pragma unroll
        for (int i = 0; i < 2; i++) {
            int row = m0 + (ty << 1) + i;
            int n   = n0 + (tx << 1);
            float lr = g_lr[row];
            float2 vv = *(const float2*)&g_v[row * DD + n];
            float2 r = {lr * (acc[i][0] + b2[n]     - vv.x),
                        lr * (acc[i][1] + b2[n + 1] - vv.y)};
            *(float2*)&g_g2[row * DD + n] = r;
        }
    }
    gbar();

    // ================= P4: g1 = (g2 @ W2) * silu_bwd(Z1)  (128 tiles) ==========
    for (int t = blockIdx.x; t < 128; t += GRID) {
        int m0 = (t & 15) * 32, n0 = (t >> 4) * 32;
        float acc[2][2] = {};
        gemm<false>(g_g2, DD, W2, HH, DD, m0, n0, acc, sm, tid, ty, tx);
        #pragma unroll
        for (int i = 0; i < 2; i++) {
            int row = m0 + (ty << 1) + i;
            int n   = n0 + (tx << 1);
            float2 z = *(const float2*)&g_Z1[row * HH + n];
            float sg0 = sigmoid_f(z.x), sg1 = sigmoid_f(z.y);
            float s0 = z.x * sg0,      s1 = z.y * sg1;
            float sb0 = s0 + sg0 * (1.f - s0);
            float sb1 = s1 + sg1 * (1.f - s1);
            float2 r = {acc[i][0] * sb0, acc[i][1] * sb1};
            *(float2*)&g_g1[row * HH + n] = r;
        }
    }
    gbar();

    // ================= P5: Xq2 = silu(A1 @ g1 + wdf*(q W1^T + b1)) (128 tiles) =
    for (int t = blockIdx.x; t < 128; t += GRID) {
        int b = t >> 6, t64 = t & 63;
        int l0 = (t64 & 7) * 32, n0 = (t64 >> 3) * 32;
        float acc1[2][2] = {}, acc2[2][2] = {};
        gemm<false>(g_A + b * LL * LL, LL, g_g1 + b * LL * HH, HH,
                    l0 + 32 /*causal*/, l0, n0, acc1, sm, tid, ty, tx);
        gemm<true>(g_q + b * LL * DD, DD, W1, DD, DD, l0, n0, acc2, sm, tid, ty, tx);
        #pragma unroll
        for (int i = 0; i < 2; i++) {
            int l = l0 + (ty << 1) + i;
            int n = n0 + (tx << 1);
            float wdf = g_wdf[b * LL + l];
            float z0 = acc1[i][0] + wdf * (acc2[i][0] + b1[n]);
            float z1 = acc1[i][1] + wdf * (acc2[i][1] + b1[n + 1]);
            *(float2*)&g_Xq2[(b * LL + l) * HH + n] =
                {z0 * sigmoid_f(z0), z1 * sigmoid_f(z1)};
        }
    }
    gbar();

    // ================= P6: A2 = C.(Xq2 X2^T + 1)  (72 tiles) ===================
    for (int t = blockIdx.x; t < 72; t += GRID) {
        int b = t / 36;
        int i, j; tri_map(t % 36, i, j);
        int l0 = i * 32, m0 = j * 32;
        float acc[2][2] = {};
        gemm<true>(g_Xq2 + b * LL * HH, HH, g_X2 + b * LL * HH, HH,
                   HH, l0, m0, acc, sm, tid, ty, tx);
        #pragma unroll
        for (int ii = 0; ii < 2; ii++) {
            int l = l0 + (ty << 1) + ii;
            int mm = m0 + (tx << 1);
            float2 cc = *(const float2*)&g_C[(b * LL + l) * LL + mm];
            float2 r = {cc.x * (acc[ii][0] + 1.f), cc.y * (acc[ii][1] + 1.f)};
            *(float2*)&g_A[(b * LL + l) * LL + mm] = r;
        }
    }
    gbar();

    // ================= P7: out = A2 @ g2 + wdf*(Xq2 W2^T + b2)  (64 tiles) =====
    for (int t = blockIdx.x; t < 64; t += GRID) {
        int b = t >> 5, t32 = t & 31;
        int l0 = (t32 & 7) * 32, n0 = (t32 >> 3) * 32;
        float acc1[2][2] = {}, acc2[2][2] = {};
        gemm<false>(g_A + b * LL * LL, LL, g_g2 + b * LL * DD, DD,
                    l0 + 32 /*causal*/, l0, n0, acc1, sm, tid, ty, tx);
        gemm<true>(g_Xq2 + b * LL * HH, HH, W2, HH, HH, l0, n0, acc2, sm, tid, ty, tx);
        #pragma unroll
        for (int i = 0; i < 2; i++) {
            int l = l0 + (ty << 1) + i;
            int n = n0 + (tx << 1);
            float wdf = g_wdf[b * LL + l];
            float2 r = {acc1[i][0] + wdf * (acc2[i][0] + b2[n]),
                        acc1[i][1] + wdf * (acc2[i][1] + b2[n + 1])};
            *(float2*)&out[(b * LL + l) * DD + n] = r;
        }
    }
}

// ================= launch ======================================================
extern "C" void kernel_launch(void* const* d_in, const int* in_sizes, int n_in,
                              void* d_out, int out_size)
{
    (void)in_sizes; (void)n_in; (void)out_size;
    fused<<<GRID, 256>>>(
        (const float*)d_in[0],
        (const float*)d_in[1],  (const float*)d_in[2],
        (const float*)d_in[3],  (const float*)d_in[4],
        (const float*)d_in[5],  (const float*)d_in[6],
        (const float*)d_in[7],  (const float*)d_in[8],
        (const float*)d_in[9],  (const float*)d_in[10],
        (const float*)d_in[11], (const float*)d_in[12],
        (const float*)d_in[13], (const float*)d_in[14],
        (const float*)d_in[15], (const float*)d_in[16],
        (float*)d_out);
}

// round 9
// speedup vs baseline: 5.3855x; 1.0228x over previous
#include <cuda_runtime.h>
#include <math.h>

#define BB 2
#define LL 256
#define DD 128
#define HH 256
#define NTOK (BB*LL)
#define GRID 296            // 148 SMs x 2 CTAs, all co-resident
#define BUFSZ 544           // 16 rows * 34 stride

// ---------------- scratch (static device globals; no allocation) ----------------
__device__ __align__(16) float g_q  [NTOK*DD];
__device__ __align__(16) float g_k  [NTOK*DD];
__device__ __align__(16) float g_v  [NTOK*DD];
__device__ __align__(16) float g_Z1 [NTOK*HH];
__device__ __align__(16) float g_X2 [NTOK*HH];
__device__ __align__(16) float g_g1 [NTOK*HH];
__device__ __align__(16) float g_g2 [NTOK*DD];
__device__ __align__(16) float g_Xq2[NTOK*HH];
__device__ __align__(16) float g_C  [BB*LL*LL];
__device__ __align__(16) float g_A  [BB*LL*LL];
__device__ float g_lr [NTOK];
__device__ float g_wdf[NTOK];
__device__ unsigned g_cnt = 0;
__device__ unsigned g_gen = 0;

__device__ __forceinline__ float softplus_f(float z) {
    return fmaxf(z, 0.f) + log1pf(__expf(-fabsf(z)));
}
__device__ __forceinline__ float sigmoid_f(float z) {
    return 1.f / (1.f + __expf(-z));
}

// sense-reversing grid barrier (all GRID blocks resident)
__device__ __forceinline__ void gbar() {
    __syncthreads();
    if (threadIdx.x == 0) {
        __threadfence();
        unsigned gen = *(volatile unsigned*)&g_gen;
        unsigned prev = atomicAdd(&g_cnt, 1u);
        if (prev == GRID - 1) {
            g_cnt = 0;
            __threadfence();
            *(volatile unsigned*)&g_gen = gen + 1;
        } else {
            while (*(volatile unsigned*)&g_gen == gen) __nanosleep(32);
            __threadfence();
        }
    }
    __syncthreads();
}

// ---------------- 32x32 tile GEMM, BK=16, 256 thr, 2x2 micro, double-buffered --
__device__ __forceinline__ void mma16(const float* __restrict__ As,
                                      const float* __restrict__ Bs,
                                      int ty, int tx, float acc[2][2])
{
    #pragma unroll
    for (int k = 0; k < 16; k++) {
        float2 a = *(const float2*)(As + k * 34 + (ty << 1));
        float2 b = *(const float2*)(Bs + k * 34 + (tx << 1));
        acc[0][0] = fmaf(a.x, b.x, acc[0][0]);
        acc[0][1] = fmaf(a.x, b.y, acc[0][1]);
        acc[1][0] = fmaf(a.y, b.x, acc[1][0]);
        acc[1][1] = fmaf(a.y, b.y, acc[1][1]);
    }
}

// store one thread's staged float4 into buffer (transposed for A / TB-B)
template<bool TB>
__device__ __forceinline__ void stsv(float* buf, float4 v, bool isA,
                                     int r, int f4, int kn, int n4)
{
    float* As = buf;
    float* Bs = buf + BUFSZ;
    if (isA) {
        As[(f4+0)*34 + r] = v.x; As[(f4+1)*34 + r] = v.y;
        As[(f4+2)*34 + r] = v.z; As[(f4+3)*34 + r] = v.w;
    } else if (TB) {
        Bs[(f4+0)*34 + r] = v.x; Bs[(f4+1)*34 + r] = v.y;
        Bs[(f4+2)*34 + r] = v.z; Bs[(f4+3)*34 + r] = v.w;
    } else {
        float2 lo = {v.x, v.y}, hi = {v.z, v.w};
        *(float2*)&Bs[kn*34 + n4]     = lo;
        *(float2*)&Bs[kn*34 + n4 + 2] = hi;
    }
}

// C += A(MxK row-major, tile m0) @ B ; TB: B is N rows of length K (B^T)
template<bool TB>
__device__ __forceinline__ void gemm(const float* __restrict__ A, int lda,
                                     const float* __restrict__ B, int ldb,
                                     int K, int m0, int n0,
                                     float acc[2][2], float* sm,
                                     int tid, int ty, int tx)
{
    const int t7  = tid & 127;
    const int r   = t7 >> 2;         // 0..31
    const int f4  = (t7 & 3) << 2;   // 0,4,8,12
    const int kn  = t7 >> 3;         // 0..15
    const int n4  = (t7 & 7) << 2;   // 0..28
    const bool isA = tid < 128;

    const int nk = K >> 4;
    float4 v;
    if (isA)     v = *(const float4*)(A + (m0 + r) * lda + f4);
    else if (TB) v = *(const float4*)(B + (n0 + r) * ldb + f4);
    else         v = *(const float4*)(B + kn * ldb + n0 + n4);
    stsv<TB>(sm, v, isA, r, f4, kn, n4);
    __syncthreads();

    for (int kt = 0; kt < nk; kt++) {
        const int k0n = (kt + 1) << 4;
        if (kt + 1 < nk) {
            if (isA)     v = *(const float4*)(A + (m0 + r) * lda + k0n + f4);
            else if (TB) v = *(const float4*)(B + (n0 + r) * ldb + k0n + f4);
            else         v = *(const float4*)(B + (k0n + kn) * ldb + n0 + n4);
        }
        const float* buf = sm + (kt & 1) * (2 * BUFSZ);
        mma16(buf, buf + BUFSZ, ty, tx, acc);
        if (kt + 1 < nk)
            stsv<TB>(sm + ((kt + 1) & 1) * (2 * BUFSZ), v, isA, r, f4, kn, n4);
        __syncthreads();
    }
}

// map t in [0,36) to lower-triangular (i,j), j<=i, i in [0,8)
__device__ __forceinline__ void tri_map(int t, int& i, int& j) {
    i = 0;
    while ((i + 1) * (i + 2) / 2 <= t) i++;
    j = t - i * (i + 1) / 2;
}

// ================= fused persistent kernel =====================================
__global__ void __launch_bounds__(256, 2) fused(
    const float* __restrict__ x,
    const float* __restrict__ W1, const float* __restrict__ b1,
    const float* __restrict__ W2, const float* __restrict__ b2,
    const float* __restrict__ Wq, const float* __restrict__ bq,
    const float* __restrict__ Wk, const float* __restrict__ bk,
    const float* __restrict__ Wv, const float* __restrict__ bv,
    const float* __restrict__ Wlr, const float* __restrict__ blr,
    const float* __restrict__ Wm,  const float* __restrict__ bm,
    const float* __restrict__ Wwd, const float* __restrict__ bwd,
    float* __restrict__ out)
{
    __shared__ float sm[4 * BUFSZ];   // double-buffered As|Bs pair
    const int tid = threadIdx.x;
    const int ty = tid >> 4, tx = tid & 15;
    const int bid = blockIdx.x;

    // ===== P1: qkv GEMM (192 tiles) + gates/scan/C (blocks 294,295) ============
    if (bid < 192) {
        int m0 = (bid & 15) * 32;
        int c0 = (bid >> 4) * 32;
        int sel = c0 >> 7;
        int n0  = c0 & 127;
        const float* W    = (sel == 0) ? Wq : (sel == 1) ? Wk : Wv;
        const float* bias = (sel == 0) ? bq : (sel == 1) ? bk : bv;
        float* o          = (sel == 0) ? g_q : (sel == 1) ? g_k : g_v;
        float acc[2][2] = {};
        gemm<true>(x, DD, W, DD, DD, m0, n0, acc, sm, tid, ty, tx);
        #pragma unroll
        for (int i = 0; i < 2; i++) {
            int row = m0 + (ty << 1) + i;
            int n   = n0 + (tx << 1);
            float2 r = {acc[i][0] + bias[n], acc[i][1] + bias[n + 1]};
            *(float2*)&o[row * DD + n] = r;
        }
    } else if (bid >= 294) {
        int b = bid - 294;
        int m = tid;
        const float* xr = x + (b * LL + m) * DD;
        float s0 = 0.f, s1 = 0.f, s2 = 0.f;
        #pragma unroll 4
        for (int j = 0; j < DD; j++) {
            float xv = xr[j];
            s0 = fmaf(xv, Wlr[j], s0);
            s1 = fmaf(xv, Wm [j], s1);
            s2 = fmaf(xv, Wwd[j], s2);
        }
        g_lr[b * LL + m] = softplus_f(s0 + blr[0]);
        float a = sigmoid_f(s1 + bm[0]);
        float d = sigmoid_f(s2 + bwd[0]);
        float* ds  = sm;
        float* as_ = sm + 256;
        float* p   = sm + 512;
        ds[m] = d; as_[m] = a; p[m] = d;
        __syncthreads();
        for (int off = 1; off < LL; off <<= 1) {
            float v = (m >= off) ? p[m - off] : 1.f;
            __syncthreads();
            p[m] *= v;
            __syncthreads();
        }
        g_wdf[b * LL + m] = p[m];
        // C[l,m] = d_l*C[l-1,m] + prod_{m<i<=l} a_i ; zero above diagonal
        float* Cb = g_C + b * LL * LL;
        float c = 0.f, e = 0.f;
        for (int l = 0; l < LL; l++) {
            e *= as_[l];
            if (l == m) e = 1.f;
            c = fmaf(ds[l], c, e);
            Cb[l * LL + m] = c;
        }
        __syncthreads();
    }
    gbar();

    // ===== P2: Z1/X2 (128) + A1 = C.(qk^T+1) (72 tri tiles) ====================
    if (bid < 128) {
        int m0 = (bid & 15) * 32, n0 = (bid >> 4) * 32;
        float acc[2][2] = {};
        gemm<true>(g_k, DD, W1, DD, DD, m0, n0, acc, sm, tid, ty, tx);
        #pragma unroll
        for (int i = 0; i < 2; i++) {
            int row = m0 + (ty << 1) + i;
            int n   = n0 + (tx << 1);
            float z0 = acc[i][0] + b1[n];
            float z1 = acc[i][1] + b1[n + 1];
            *(float2*)&g_Z1[row * HH + n] = {z0, z1};
            *(float2*)&g_X2[row * HH + n] = {z0 * sigmoid_f(z0), z1 * sigmoid_f(z1)};
        }
    } else if (bid < 200) {
        int tt = bid - 128;
        int b = tt / 36;
        int i, j; tri_map(tt % 36, i, j);
        int l0 = i * 32, m0 = j * 32;
        float acc[2][2] = {};
        gemm<true>(g_q + b * LL * DD, DD, g_k + b * LL * DD, DD, DD, l0, m0,
                   acc, sm, tid, ty, tx);
        #pragma unroll
        for (int ii = 0; ii < 2; ii++) {
            int l = l0 + (ty << 1) + ii;
            int mm = m0 + (tx << 1);
            float2 cc = *(const float2*)&g_C[(b * LL + l) * LL + mm];
            float2 r = {cc.x * (acc[ii][0] + 1.f), cc.y * (acc[ii][1] + 1.f)};
            *(float2*)&g_A[(b * LL + l) * LL + mm] = r;
        }
    }
    gbar();

    // ===== P3: g2 = lr*(X2 W2^T + b2 - v) (64 tiles) ===========================
    if (bid < 64) {
        int m0 = (bid & 15) * 32, n0 = (bid >> 4) * 32;
        float acc[2][2] = {};
        gemm<true>(g_X2, HH, W2, HH, HH, m0, n0, acc, sm, tid, ty, tx);
        #pragma unroll
        for (int i = 0; i < 2; i++) {
            int row = m0 + (ty << 1) + i;
            int n   = n0 + (tx << 1);
            float lr = g_lr[row];
            float2 vv = *(const float2*)&g_v[row * DD + n];
            float2 r = {lr * (acc[i][0] + b2[n]     - vv.x),
                        lr * (acc[i][1] + b2[n + 1] - vv.y)};
            *(float2*)&g_g2[row * DD + n] = r;
        }
    }
    gbar();

    // ===== P4: g1 = (g2 @ W2) * silu_bwd(Z1) (128 tiles) =======================
    if (bid < 128) {
        int m0 = (bid & 15) * 32, n0 = (bid >> 4) * 32;
        float acc[2][2] = {};
        gemm<false>(g_g2, DD, W2, HH, DD, m0, n0, acc, sm, tid, ty, tx);
        #pragma unroll
        for (int i = 0; i < 2; i++) {
            int row = m0 + (ty << 1) + i;
            int n   = n0 + (tx << 1);
            float2 z = *(const float2*)&g_Z1[row * HH + n];
            float sg0 = sigmoid_f(z.x), sg1 = sigmoid_f(z.y);
            float s0 = z.x * sg0,      s1 = z.y * sg1;
            float sb0 = s0 + sg0 * (1.f - s0);
            float sb1 = s1 + sg1 * (1.f - s1);
            float2 r = {acc[i][0] * sb0, acc[i][1] * sb1};
            *(float2*)&g_g1[row * HH + n] = r;
        }
    }
    gbar();

    // ===== P5: Xq2 = silu(A1 @ g1 + wdf*(q W1^T + b1)) (128 tiles) =============
    if (bid < 128) {
        int b = bid >> 6, t64 = bid & 63;
        int l0 = (t64 & 7) * 32, n0 = (t64 >> 3) * 32;
        float acc1[2][2] = {}, acc2[2][2] = {};
        gemm<false>(g_A + b * LL * LL, LL, g_g1 + b * LL * HH, HH,
                    l0 + 32 /*causal*/, l0, n0, acc1, sm, tid, ty, tx);
        gemm<true>(g_q + b * LL * DD, DD, W1, DD, DD, l0, n0, acc2, sm, tid, ty, tx);
        #pragma unroll
        for (int i = 0; i < 2; i++) {
            int l = l0 + (ty << 1) + i;
            int n = n0 + (tx << 1);
            float wdf = g_wdf[b * LL + l];
            float z0 = acc1[i][0] + wdf * (acc2[i][0] + b1[n]);
            float z1 = acc1[i][1] + wdf * (acc2[i][1] + b1[n + 1]);
            *(float2*)&g_Xq2[(b * LL + l) * HH + n] =
                {z0 * sigmoid_f(z0), z1 * sigmoid_f(z1)};
        }
    }
    gbar();

    // ===== P6: A2 = C.(Xq2 X2^T + 1) (72 tri tiles) ============================
    if (bid < 72) {
        int b = bid / 36;
        int i, j; tri_map(bid % 36, i, j);
        int l0 = i * 32, m0 = j * 32;
        float acc[2][2] = {};
        gemm<true>(g_Xq2 + b * LL * HH, HH, g_X2 + b * LL * HH, HH,
                   HH, l0, m0, acc, sm, tid, ty, tx);
        #pragma unroll
        for (int ii = 0; ii < 2; ii++) {
            int l = l0 + (ty << 1) + ii;
            int mm = m0 + (tx << 1);
            float2 cc = *(const float2*)&g_C[(b * LL + l) * LL + mm];
            float2 r = {cc.x * (acc[ii][0] + 1.f), cc.y * (acc[ii][1] + 1.f)};
            *(float2*)&g_A[(b * LL + l) * LL + mm] = r;
        }
    }
    gbar();

    // ===== P7: out = A2 @ g2 + wdf*(Xq2 W2^T + b2) (64 tiles) ==================
    if (bid < 64) {
        int b = bid >> 5, t32 = bid & 31;
        int l0 = (t32 & 7) * 32, n0 = (t32 >> 3) * 32;
        float acc1[2][2] = {}, acc2[2][2] = {};
        gemm<false>(g_A + b * LL * LL, LL, g_g2 + b * LL * DD, DD,
                    l0 + 32 /*causal*/, l0, n0, acc1, sm, tid, ty, tx);
        gemm<true>(g_Xq2 + b * LL * HH, HH, W2, HH, HH, l0, n0, acc2, sm, tid, ty, tx);
        #pragma unroll
        for (int i = 0; i < 2; i++) {
            int l = l0 + (ty << 1) + i;
            int n = n0 + (tx << 1);
            float wdf = g_wdf[b * LL + l];
            float2 r = {acc1[i][0] + wdf * (acc2[i][0] + b2[n]),
                        acc1[i][1] + wdf * (acc2[i][1] + b2[n + 1])};
            *(float2*)&out[(b * LL + l) * DD + n] = r;
        }
    }
}

// ================= launch ======================================================
extern "C" void kernel_launch(void* const* d_in, const int* in_sizes, int n_in,
                              void* d_out, int out_size)
{
    (void)in_sizes; (void)n_in; (void)out_size;
    fused<<<GRID, 256>>>(
        (const float*)d_in[0],
        (const float*)d_in[1],  (const float*)d_in[2],
        (const float*)d_in[3],  (const float*)d_in[4],
        (const float*)d_in[5],  (const float*)d_in[6],
        (const float*)d_in[7],  (const float*)d_in[8],
        (const float*)d_in[9],  (const float*)d_in[10],
        (const float*)d_in[11], (const float*)d_in[12],
        (const float*)d_in[13], (const float*)d_in[14],
        (const float*)d_in[15], (const float*)d_in[16],
        (float*)d_out);
}